// round 16
// baseline (speedup 1.0000x reference)
#include <cuda_runtime.h>
#include <cuda_bf16.h>
#include <math.h>
#include <stdint.h>

#define NB   100
#define NPG  500
#define NN   (NB*NPG)     // 50000 nodes
#define NE   (NN*12)      // 600000 edges
#define EPG  (NPG*12)     // 6000 edges per graph (contiguous)
#define H    128
#define K1   250
#define K2   125
#define K3   63

// ---------------- scratch (device globals; no allocation) ----------------
__device__ float g_h    [NN*H];        // pre-pool features
__device__ float g_p1   [NB*K1*H];     // pooled buffer A
__device__ float g_p2   [NB*K2*H];     // pooled buffer B
__device__ unsigned short g_mh[NN*H];  // mean hi plane (bf16 bits)
__device__ unsigned short g_ml[NN*H];  // mean lo plane
__device__ unsigned short g_xh[NN*H];  // x hi plane
__device__ unsigned short g_xl[NN*H];  // x lo plane
__device__ int   g_srcB [NE];
__device__ int   g_dstB [NE];
__device__ int   g_srcC [NE];
__device__ int   g_dstC [NE];
__device__ int   g_gecB [NB];
__device__ int   g_gecC [NB];
__device__ float g_z    [NB*2*H];

// ---------------- helpers ----------------
__device__ __forceinline__ unsigned short bf_hi(float v) {
    return __bfloat16_as_ushort(__float2bfloat16_rn(v));
}
__device__ __forceinline__ void bf_split(float v, unsigned short& h, unsigned short& l) {
    h = bf_hi(v);
    float rem = v - __bfloat162float(__ushort_as_bfloat16(h));
    l = bf_hi(rem);
}
__device__ __forceinline__ uint32_t smem_u32(const void* p) {
    uint32_t a;
    asm("{ .reg .u64 t; cvta.to.shared.u64 t, %1; cvt.u32.u64 %0, t; }" : "=r"(a) : "l"(p));
    return a;
}
__device__ __forceinline__ void cp_async16(uint32_t saddr, const void* gptr, int szvalid) {
    asm volatile("cp.async.cg.shared.global [%0], [%1], 16, %2;"
                 :: "r"(saddr), "l"(gptr), "r"(szvalid));
}
#define CP_COMMIT() asm volatile("cp.async.commit_group;" ::: "memory")
#define CP_WAIT0()  asm volatile("cp.async.wait_group 0;" ::: "memory")

// ---------------- kernels ----------------

// one-shot: x (fp32) -> bf16 hi/lo planes
__global__ void k_convert_x(const float* __restrict__ x) {
    int i = blockIdx.x * blockDim.x + threadIdx.x;
    if (i >= NN * H / 4) return;
    float4 v = reinterpret_cast<const float4*>(x)[i];
    ushort4 hv, lv;
    bf_split(v.x, hv.x, lv.x);
    bf_split(v.y, hv.y, lv.y);
    bf_split(v.z, hv.z, lv.z);
    bf_split(v.w, hv.w, lv.w);
    reinterpret_cast<ushort4*>(g_xh)[i] = hv;
    reinterpret_cast<ushort4*>(g_xl)[i] = lv;
}

// One block per graph, 1024 threads: smem degree count -> smem scan ->
// smem CSR fill -> gather neighbor means; writes mean as bf16 hi/lo planes.
__global__ void __launch_bounds__(1024) k_aggregate(
        const int* __restrict__ src, const int* __restrict__ dst,
        const int* __restrict__ gec, int fixed,
        const float* __restrict__ xin, int n_per) {
    extern __shared__ int sm[];
    int* s_src = sm;                 // [EPG]
    int* s_dst = sm + EPG;           // [EPG] (local dst)
    int* s_csr = sm + 2 * EPG;       // [EPG]
    int* s_deg = sm + 3 * EPG;       // [512]
    int* s_st  = s_deg + 512;        // [512]
    int* s_cur = s_st + 512;         // [512]

    int b = blockIdx.x, t = threadIdx.x;
    int ne    = fixed ? EPG : gec[b];
    int ebase = b * EPG;
    int nbase = b * n_per;

    if (t < 512) s_deg[t] = 0;
    __syncthreads();

    for (int i = t; i < ne; i += blockDim.x) {
        int s = src[ebase + i];
        int d = dst[ebase + i] - nbase;
        s_src[i] = s;
        s_dst[i] = d;
        atomicAdd(&s_deg[d], 1);
    }
    __syncthreads();

    int v = (t < 512) ? s_deg[t] : 0;
    if (t < 512) s_st[t] = v;
    __syncthreads();
    #pragma unroll
    for (int o = 1; o < 512; o <<= 1) {
        int u = (t >= o && t < 512) ? s_st[t - o] : 0;
        __syncthreads();
        if (t < 512) s_st[t] += u;
        __syncthreads();
    }
    if (t < 512) {
        int excl = s_st[t] - v;
        s_st[t]  = excl;
        s_cur[t] = excl;
    }
    __syncthreads();

    for (int i = t; i < ne; i += blockDim.x) {
        int pos = atomicAdd(&s_cur[s_dst[i]], 1);
        s_csr[pos] = s_src[i];
    }
    __syncthreads();

    int lane = t & 31, wid = t >> 5, nw = blockDim.x >> 5;
    for (int node = wid; node < n_per; node += nw) {
        int deg = s_deg[node], st = s_st[node];
        float4 a0 = {0.f,0.f,0.f,0.f}, a1 = a0, a2 = a0, a3 = a0;
        int j = 0;
        for (; j + 4 <= deg; j += 4) {
            int s0 = s_csr[st + j];
            int s1 = s_csr[st + j + 1];
            int s2 = s_csr[st + j + 2];
            int s3 = s_csr[st + j + 3];
            float4 v0 = reinterpret_cast<const float4*>(xin + (size_t)s0 * H)[lane];
            float4 v1 = reinterpret_cast<const float4*>(xin + (size_t)s1 * H)[lane];
            float4 v2 = reinterpret_cast<const float4*>(xin + (size_t)s2 * H)[lane];
            float4 v3 = reinterpret_cast<const float4*>(xin + (size_t)s3 * H)[lane];
            a0.x += v0.x; a0.y += v0.y; a0.z += v0.z; a0.w += v0.w;
            a1.x += v1.x; a1.y += v1.y; a1.z += v1.z; a1.w += v1.w;
            a2.x += v2.x; a2.y += v2.y; a2.z += v2.z; a2.w += v2.w;
            a3.x += v3.x; a3.y += v3.y; a3.z += v3.z; a3.w += v3.w;
        }
        for (; j < deg; j++) {
            int s0 = s_csr[st + j];
            float4 v0 = reinterpret_cast<const float4*>(xin + (size_t)s0 * H)[lane];
            a0.x += v0.x; a0.y += v0.y; a0.z += v0.z; a0.w += v0.w;
        }
        float invd = 1.0f / fmaxf((float)deg, 1.0f);
        float4 o;
        o.x = (a0.x + a1.x + a2.x + a3.x) * invd;
        o.y = (a0.y + a1.y + a2.y + a3.y) * invd;
        o.z = (a0.z + a1.z + a2.z + a3.z) * invd;
        o.w = (a0.w + a1.w + a2.w + a3.w) * invd;
        ushort4 hv, lv;
        bf_split(o.x, hv.x, lv.x);
        bf_split(o.y, hv.y, lv.y);
        bf_split(o.z, hv.z, lv.z);
        bf_split(o.w, hv.w, lv.w);
        size_t off = (size_t)(nbase + node) * H + lane * 4;
        *reinterpret_cast<ushort4*>(g_mh + off) = hv;
        *reinterpret_cast<ushort4*>(g_ml + off) = lv;
    }
}

// ---- mma.sync bf16 SAGE GEMM: out = relu( [mean||x] @ [Wl;Wr] + bl ) ----
// A planes (mean/x, hi/lo) are pre-converted bf16 in global; staging is pure
// cp.async copy. 3 cross terms (hh, hl, lh); ll dropped (<=2^-16 rel).
// 512 threads, 16 warps as 4(m)x4(n), warp tile 32x32.
#define AP 136
#define WP 264
#define SM_WH 512
#define SM_WL (512 + 128*WP*2)
#define SM_AH (512 + 2*128*WP*2)
#define SM_AL (512 + 2*128*WP*2 + 128*AP*2)
#define SAGE_SMEM_TC (512 + 2*128*WP*2 + 2*128*AP*2)   // 205312 B

#define MMA_BF16(c0,c1,c2,c3, a0,a1,a2,a3, b0,b1) \
    asm volatile("mma.sync.aligned.m16n8k16.row.col.f32.bf16.bf16.f32 " \
        "{%0,%1,%2,%3}, {%4,%5,%6,%7}, {%8,%9}, {%0,%1,%2,%3};" \
        : "+f"(c0), "+f"(c1), "+f"(c2), "+f"(c3) \
        : "r"(a0), "r"(a1), "r"(a2), "r"(a3), "r"(b0), "r"(b1))

__global__ void __launch_bounds__(512) k_sage(const float* __restrict__ Wl,
                                              const float* __restrict__ bl,
                                              const float* __restrict__ Wr,
                                              float* __restrict__ out, int n) {
    extern __shared__ char smc[];
    float* sb = (float*)smc;                             // [128] bias
    unsigned short* sWH = (unsigned short*)(smc + SM_WH);
    unsigned short* sWL = (unsigned short*)(smc + SM_WL);
    unsigned short* sAH = (unsigned short*)(smc + SM_AH);
    unsigned short* sAL = (unsigned short*)(smc + SM_AL);
    uint32_t saH = smem_u32(sAH);
    uint32_t saL = smem_u32(sAL);

    int t = threadIdx.x;
    int wid = t >> 5, lane = t & 31;
    int g = lane >> 2, tq = lane & 3;
    int wm = wid & 3;             // 0..3 : m-offset 32*wm
    int wn = wid >> 2;            // 0..3 : n-offset 32*wn

    if (t < 128) sb[t] = bl[t];

    // Stage W transposed: Wt[n][kk], kk = m*128 + k; hi/lo bf16 split. Once per block.
    for (int m = 0; m < 2; m++) {
        const float* W = m ? Wr : Wl;
        for (int i = t; i < 128 * 32; i += 512) {
            int k = i >> 5, n4 = i & 31;
            float4 v = *reinterpret_cast<const float4*>(W + k * 128 + n4 * 4);
            int kk = m * 128 + k;
            float vv[4] = {v.x, v.y, v.z, v.w};
            #pragma unroll
            for (int e = 0; e < 4; e++) {
                int nn = n4 * 4 + e;
                unsigned short hb, lb;
                bf_split(vv[e], hb, lb);
                sWH[nn * WP + kk] = hb;
                sWL[nn * WP + kk] = lb;
            }
        }
    }
    __syncthreads();

    int ntiles = (n + 127) / 128;

    for (int tile = blockIdx.x; tile < ntiles; tile += gridDim.x) {
        int row0 = tile * 128;

        float acc[2][4][4];
        #pragma unroll
        for (int mt = 0; mt < 2; mt++)
            #pragma unroll
            for (int nt = 0; nt < 4; nt++)
                #pragma unroll
                for (int e = 0; e < 4; e++) acc[mt][nt][e] = 0.f;

        #pragma unroll
        for (int ph = 0; ph < 2; ph++) {
            const unsigned short* srcH = ph ? g_xh : g_mh;
            const unsigned short* srcL = ph ? g_xl : g_ml;
            __syncthreads();          // previous phase fragment readers done
            // stage A half: pure cp.async copy, 16B chunks (8 bf16)
            for (int i = t; i < 128 * 16; i += 512) {
                int r = i >> 4, c8 = (i & 15) << 3;
                int grow = row0 + r;
                int valid = (grow < n);
                size_t goff = (size_t)(valid ? grow : 0) * H + c8;
                int sz = valid ? 16 : 0;
                uint32_t soff = (uint32_t)(r * AP + c8) * 2;
                cp_async16(saH + soff, srcH + goff, sz);
                cp_async16(saL + soff, srcL + goff, sz);
            }
            CP_COMMIT();
            CP_WAIT0();
            __syncthreads();

            #pragma unroll
            for (int s = 0; s < 8; s++) {
                int k0 = s * 16;                 // local k within half
                int kg = ph * 128 + k0;          // global k within [0,256)
                // B fragments (4 n-tiles, hi+lo)
                uint32_t bh[4][2], blo[4][2];
                #pragma unroll
                for (int nt = 0; nt < 4; nt++) {
                    int nn = wn * 32 + nt * 8 + g;
                    bh[nt][0]  = *reinterpret_cast<const uint32_t*>(sWH + nn * WP + kg + 2 * tq);
                    bh[nt][1]  = *reinterpret_cast<const uint32_t*>(sWH + nn * WP + kg + 2 * tq + 8);
                    blo[nt][0] = *reinterpret_cast<const uint32_t*>(sWL + nn * WP + kg + 2 * tq);
                    blo[nt][1] = *reinterpret_cast<const uint32_t*>(sWL + nn * WP + kg + 2 * tq + 8);
                }
                // A fragments (2 m-tiles, hi+lo)
                uint32_t ah[2][4], alo[2][4];
                #pragma unroll
                for (int mt = 0; mt < 2; mt++) {
                    int m0 = wm * 32 + mt * 16 + g;
                    ah[mt][0]  = *reinterpret_cast<const uint32_t*>(sAH + m0 * AP + k0 + 2 * tq);
                    ah[mt][1]  = *reinterpret_cast<const uint32_t*>(sAH + (m0 + 8) * AP + k0 + 2 * tq);
                    ah[mt][2]  = *reinterpret_cast<const uint32_t*>(sAH + m0 * AP + k0 + 2 * tq + 8);
                    ah[mt][3]  = *reinterpret_cast<const uint32_t*>(sAH + (m0 + 8) * AP + k0 + 2 * tq + 8);
                    alo[mt][0] = *reinterpret_cast<const uint32_t*>(sAL + m0 * AP + k0 + 2 * tq);
                    alo[mt][1] = *reinterpret_cast<const uint32_t*>(sAL + (m0 + 8) * AP + k0 + 2 * tq);
                    alo[mt][2] = *reinterpret_cast<const uint32_t*>(sAL + m0 * AP + k0 + 2 * tq + 8);
                    alo[mt][3] = *reinterpret_cast<const uint32_t*>(sAL + (m0 + 8) * AP + k0 + 2 * tq + 8);
                }
                // 3 passes: hh, hl, lh
                #pragma unroll
                for (int mt = 0; mt < 2; mt++)
                    #pragma unroll
                    for (int nt = 0; nt < 4; nt++)
                        MMA_BF16(acc[mt][nt][0], acc[mt][nt][1], acc[mt][nt][2], acc[mt][nt][3],
                                 ah[mt][0], ah[mt][1], ah[mt][2], ah[mt][3], bh[nt][0], bh[nt][1]);
                #pragma unroll
                for (int mt = 0; mt < 2; mt++)
                    #pragma unroll
                    for (int nt = 0; nt < 4; nt++)
                        MMA_BF16(acc[mt][nt][0], acc[mt][nt][1], acc[mt][nt][2], acc[mt][nt][3],
                                 ah[mt][0], ah[mt][1], ah[mt][2], ah[mt][3], blo[nt][0], blo[nt][1]);
                #pragma unroll
                for (int mt = 0; mt < 2; mt++)
                    #pragma unroll
                    for (int nt = 0; nt < 4; nt++)
                        MMA_BF16(acc[mt][nt][0], acc[mt][nt][1], acc[mt][nt][2], acc[mt][nt][3],
                                 alo[mt][0], alo[mt][1], alo[mt][2], alo[mt][3], bh[nt][0], bh[nt][1]);
            }
        }

        // epilogue: bias + relu + store
        #pragma unroll
        for (int mt = 0; mt < 2; mt++) {
            int r0 = row0 + wm * 32 + mt * 16 + g;
            #pragma unroll
            for (int nt = 0; nt < 4; nt++) {
                int c = wn * 32 + nt * 8 + 2 * tq;
                float b0v = sb[c], b1v = sb[c + 1];
                if (r0 < n) {
                    float2 o;
                    o.x = fmaxf(acc[mt][nt][0] + b0v, 0.f);
                    o.y = fmaxf(acc[mt][nt][1] + b1v, 0.f);
                    *reinterpret_cast<float2*>(out + (size_t)r0 * H + c) = o;
                }
                if (r0 + 8 < n) {
                    float2 o;
                    o.x = fmaxf(acc[mt][nt][2] + b0v, 0.f);
                    o.y = fmaxf(acc[mt][nt][3] + b1v, 0.f);
                    *reinterpret_cast<float2*>(out + (size_t)(r0 + 8) * H + c) = o;
                }
            }
        }
    }
}

// One block per graph: score + stable top-k + pool + readout + edge compact.
// Also writes pooled features as bf16 hi/lo planes (next layer's x operand).
__global__ void __launch_bounds__(512) k_pool_all(
        const float* __restrict__ h, const float* __restrict__ pw,
        int n_per, int k, int layer,
        const int* __restrict__ src, const int* __restrict__ dst,
        const int* __restrict__ gec, int fixed,
        int* __restrict__ nsrc, int* __restrict__ ndst, int* __restrict__ ngec,
        float* __restrict__ hout) {
    __shared__ float s_w[128];
    __shared__ float s_sc[512];
    __shared__ int   s_map[512];
    __shared__ int   s_perm[256];
    __shared__ float s_inv;
    __shared__ int   s_cursor;
    __shared__ float s_mx[4][128];
    __shared__ float s_sm[4][128];

    int b = blockIdx.x, t = threadIdx.x;
    int lane = t & 31, wid = t >> 5, nw = blockDim.x >> 5;
    int nbase = b * n_per;

    if (t < 128) s_w[t] = pw[t];
    if (t == 0) s_cursor = 0;
    __syncthreads();

    if (wid == 0) {
        float wn = 0.f;
        #pragma unroll
        for (int c = lane; c < 128; c += 32) { float w = s_w[c]; wn += w * w; }
        #pragma unroll
        for (int o = 16; o; o >>= 1) wn += __shfl_down_sync(0xffffffffu, wn, o);
        if (lane == 0) s_inv = rsqrtf(wn);
    }
    __syncthreads();
    float inv = s_inv;

    for (int node = wid; node < n_per; node += nw) {
        const float* row = h + (size_t)(nbase + node) * H;
        float dot = 0.f;
        #pragma unroll
        for (int c = lane; c < 128; c += 32) dot += row[c] * s_w[c];
        #pragma unroll
        for (int o = 16; o; o >>= 1) dot += __shfl_down_sync(0xffffffffu, dot, o);
        if (lane == 0) s_sc[node] = tanhf(dot * inv);
    }
    __syncthreads();

    if (t < n_per) {
        float si = s_sc[t];
        int rank = 0;
        for (int j = 0; j < n_per; j++) {
            float sj = s_sc[j];
            rank += (sj > si) || (sj == si && j < t);
        }
        if (rank < k) { s_map[t] = rank; s_perm[rank] = t; }
        else          s_map[t] = -1;
    }
    __syncthreads();

    for (int r = wid; r < k; r += nw) {
        int node = s_perm[r];
        float sc = s_sc[node];
        float4 v = reinterpret_cast<const float4*>(h + (size_t)(nbase + node) * H)[lane];
        v.x *= sc; v.y *= sc; v.z *= sc; v.w *= sc;
        size_t off = (size_t)(b * k + r) * H + lane * 4;
        *reinterpret_cast<float4*>(hout + off) = v;
        if (layer < 2) {
            ushort4 hv, lv;
            bf_split(v.x, hv.x, lv.x);
            bf_split(v.y, hv.y, lv.y);
            bf_split(v.z, hv.z, lv.z);
            bf_split(v.w, hv.w, lv.w);
            *reinterpret_cast<ushort4*>(g_xh + off) = hv;
            *reinterpret_cast<ushort4*>(g_xl + off) = lv;
        }
    }
    __syncthreads();

    {
        int q = t >> 7;
        int c = t & 127;
        float mx = -1e30f, smv = 0.f;
        for (int r = q; r < k; r += 4) {
            float v = hout[(size_t)(b * k + r) * H + c];
            mx = fmaxf(mx, v);
            smv += v;
        }
        s_mx[q][c] = mx;
        s_sm[q][c] = smv;
    }
    __syncthreads();
    if (t < 128) {
        float mx = fmaxf(fmaxf(s_mx[0][t], s_mx[1][t]), fmaxf(s_mx[2][t], s_mx[3][t]));
        float smv = s_sm[0][t] + s_sm[1][t] + s_sm[2][t] + s_sm[3][t];
        float mean = smv / (float)k;
        if (layer == 0) {
            g_z[b * 2 * H + t]     = mx;
            g_z[b * 2 * H + H + t] = mean;
        } else {
            g_z[b * 2 * H + t]     += mx;
            g_z[b * 2 * H + H + t] += mean;
        }
    }

    if (layer < 2) {
        int ne = fixed ? EPG : gec[b];
        int ebase = b * EPG;
        for (int e0 = 0; e0 < ne; e0 += blockDim.x) {
            int e = e0 + t;
            int rs = -1, rd = -1;
            if (e < ne) {
                rs = s_map[src[ebase + e] - nbase];
                rd = s_map[dst[ebase + e] - nbase];
            }
            bool act = (rs >= 0) && (rd >= 0);
            unsigned m = __ballot_sync(0xffffffffu, act);
            if (m) {
                int leader = __ffs(m) - 1;
                int base = 0;
                if (lane == leader) base = atomicAdd(&s_cursor, __popc(m));
                base = __shfl_sync(0xffffffffu, base, leader);
                if (act) {
                    int pos = base + __popc(m & ((1u << lane) - 1u));
                    nsrc[ebase + pos] = b * k + rs;
                    ndst[ebase + pos] = b * k + rd;
                }
            }
        }
        __syncthreads();
        if (t == 0) ngec[b] = s_cursor;
    }
}

// MLP head + log_softmax, one block per graph
__global__ void k_mlp(const float* __restrict__ W1, const float* __restrict__ b1,
                      const float* __restrict__ W2, const float* __restrict__ b2,
                      const float* __restrict__ W3, const float* __restrict__ b3,
                      float* __restrict__ out) {
    int b = blockIdx.x, t = threadIdx.x;
    __shared__ float zin[256], t1[128], t2[64], lg[10];
    zin[t] = g_z[b * 256 + t];
    __syncthreads();
    if (t < 128) {
        float a = b1[t];
        for (int k = 0; k < 256; k++) a += zin[k] * W1[k * 128 + t];
        t1[t] = fmaxf(a, 0.f);
    }
    __syncthreads();
    if (t < 64) {
        float a = b2[t];
        for (int k = 0; k < 128; k++) a += t1[k] * W2[k * 64 + t];
        t2[t] = fmaxf(a, 0.f);
    }
    __syncthreads();
    if (t < 10) {
        float a = b3[t];
        for (int k = 0; k < 64; k++) a += t2[k] * W3[k * 10 + t];
        lg[t] = a;
    }
    __syncthreads();
    if (t == 0) {
        float mx = -1e30f;
        for (int i = 0; i < 10; i++) mx = fmaxf(mx, lg[i]);
        float s = 0.f;
        for (int i = 0; i < 10; i++) s += expf(lg[i] - mx);
        float lse = mx + logf(s);
        for (int i = 0; i < 10; i++) out[b * 10 + i] = lg[i] - lse;
    }
}

// ---------------- host ----------------

static const int AGG_SMEM = (3 * EPG + 3 * 512) * sizeof(int);  // 78144 B

extern "C" void kernel_launch(void* const* d_in, const int* in_sizes, int n_in,
                              void* d_out, int out_size) {
    const float* x   = (const float*)d_in[0];
    const int*   ei  = (const int*)  d_in[1];
    const float* Wl1 = (const float*)d_in[2];
    const float* bl1 = (const float*)d_in[3];
    const float* Wr1 = (const float*)d_in[4];
    const float* Wl2 = (const float*)d_in[5];
    const float* bl2 = (const float*)d_in[6];
    const float* Wr2 = (const float*)d_in[7];
    const float* Wl3 = (const float*)d_in[8];
    const float* bl3 = (const float*)d_in[9];
    const float* Wr3 = (const float*)d_in[10];
    const float* pw1 = (const float*)d_in[11];
    const float* pw2 = (const float*)d_in[12];
    const float* pw3 = (const float*)d_in[13];
    const float* W1  = (const float*)d_in[14];
    const float* b1  = (const float*)d_in[15];
    const float* W2  = (const float*)d_in[16];
    const float* b2  = (const float*)d_in[17];
    const float* W3  = (const float*)d_in[18];
    const float* b3  = (const float*)d_in[19];
    float* out = (float*)d_out;

    static bool attr_set = false;
    if (!attr_set) {
        cudaFuncSetAttribute(k_sage,      cudaFuncAttributeMaxDynamicSharedMemorySize, SAGE_SMEM_TC);
        cudaFuncSetAttribute(k_aggregate, cudaFuncAttributeMaxDynamicSharedMemorySize, AGG_SMEM);
        attr_set = true;
    }

    void *p_h, *p_p1, *p_p2, *p_srcB, *p_dstB, *p_srcC, *p_dstC, *p_gecB, *p_gecC;
    cudaGetSymbolAddress(&p_h,    g_h);
    cudaGetSymbolAddress(&p_p1,   g_p1);
    cudaGetSymbolAddress(&p_p2,   g_p2);
    cudaGetSymbolAddress(&p_srcB, g_srcB);
    cudaGetSymbolAddress(&p_dstB, g_dstB);
    cudaGetSymbolAddress(&p_srcC, g_srcC);
    cudaGetSymbolAddress(&p_dstC, g_dstC);
    cudaGetSymbolAddress(&p_gecB, g_gecB);
    cudaGetSymbolAddress(&p_gecC, g_gecC);
    float* dh = (float*)p_h;

    struct Layer {
        const float *Wl, *bl, *Wr, *pw;
        const int *src, *dst, *gec;
        int fixed;
        int *nsrc, *ndst, *ngec;
        int n_in, n_per, k;
        float* pool_out;
    } layers[3] = {
        {Wl1, bl1, Wr1, pw1, ei,           ei + NE,      nullptr,       1,
         (int*)p_srcB, (int*)p_dstB, (int*)p_gecB, NN,      NPG, K1, (float*)p_p1},
        {Wl2, bl2, Wr2, pw2, (int*)p_srcB, (int*)p_dstB, (int*)p_gecB,  0,
         (int*)p_srcC, (int*)p_dstC, (int*)p_gecC, NB * K1, K1,  K2, (float*)p_p2},
        {Wl3, bl3, Wr3, pw3, (int*)p_srcC, (int*)p_dstC, (int*)p_gecC,  0,
         nullptr, nullptr, nullptr,                  NB * K2, K2,  K3, (float*)p_p1},
    };

    // one-shot conversion of the layer-1 x operand to bf16 hi/lo planes
    k_convert_x<<<(NN * H / 4 + 255) / 256, 256>>>(x);

    const float* xin = x;
    for (int l = 0; l < 3; l++) {
        const Layer& L = layers[l];
        int n = L.n_in;

        k_aggregate<<<NB, 1024, AGG_SMEM>>>(L.src, L.dst, L.gec, L.fixed, xin, L.n_per);

        int ntiles = (n + 127) / 128;
        int grid = ntiles < 148 ? ntiles : 148;
        k_sage<<<grid, 512, SAGE_SMEM_TC>>>(L.Wl, L.bl, L.Wr, dh, n);

        k_pool_all<<<NB, 512>>>(dh, L.pw, L.n_per, L.k, l,
                                L.src, L.dst, L.gec, L.fixed,
                                L.nsrc, L.ndst, L.ngec, L.pool_out);

        xin = L.pool_out;
    }

    k_mlp<<<NB, 256>>>(W1, b1, W2, b2, W3, b3, out);
}

// round 17
// speedup vs baseline: 1.0573x; 1.0573x over previous
#include <cuda_runtime.h>
#include <cuda_bf16.h>
#include <math.h>
#include <stdint.h>

#define NB   100
#define NPG  500
#define NN   (NB*NPG)     // 50000 nodes
#define NE   (NN*12)      // 600000 edges
#define EPG  (NPG*12)     // 6000 edges per graph (contiguous)
#define H    128
#define K1   250
#define K2   125
#define K3   63

// ---------------- scratch (device globals; no allocation) ----------------
__device__ float g_h    [NN*H];        // pre-pool features
__device__ float g_p1   [NB*K1*H];     // pooled buffer A
__device__ float g_p2   [NB*K2*H];     // pooled buffer B
__device__ unsigned short g_mh[NN*H];  // mean hi plane (bf16 bits)
__device__ unsigned short g_ml[NN*H];  // mean lo plane
__device__ unsigned short g_xh[NN*H];  // x hi plane
__device__ unsigned short g_xl[NN*H];  // x lo plane
__device__ int   g_srcB [NE];
__device__ int   g_dstB [NE];
__device__ int   g_srcC [NE];
__device__ int   g_dstC [NE];
__device__ int   g_gecB [NB];
__device__ int   g_gecC [NB];
__device__ float g_z    [NB*2*H];

// ---------------- helpers ----------------
__device__ __forceinline__ unsigned short bf_hi(float v) {
    return __bfloat16_as_ushort(__float2bfloat16_rn(v));
}
__device__ __forceinline__ void bf_split(float v, unsigned short& h, unsigned short& l) {
    h = bf_hi(v);
    float rem = v - __bfloat162float(__ushort_as_bfloat16(h));
    l = bf_hi(rem);
}
__device__ __forceinline__ uint32_t smem_u32(const void* p) {
    uint32_t a;
    asm("{ .reg .u64 t; cvta.to.shared.u64 t, %1; cvt.u32.u64 %0, t; }" : "=r"(a) : "l"(p));
    return a;
}
__device__ __forceinline__ void cp_async16(uint32_t saddr, const void* gptr, int szvalid) {
    asm volatile("cp.async.cg.shared.global [%0], [%1], 16, %2;"
                 :: "r"(saddr), "l"(gptr), "r"(szvalid));
}
#define CP_COMMIT() asm volatile("cp.async.commit_group;" ::: "memory")
#define CP_WAIT0()  asm volatile("cp.async.wait_group 0;" ::: "memory")

// ---------------- kernels ----------------

// one-shot: x (fp32) -> bf16 hi/lo planes
__global__ void k_convert_x(const float* __restrict__ x) {
    int i = blockIdx.x * blockDim.x + threadIdx.x;
    if (i >= NN * H / 4) return;
    float4 v = reinterpret_cast<const float4*>(x)[i];
    ushort4 hv, lv;
    bf_split(v.x, hv.x, lv.x);
    bf_split(v.y, hv.y, lv.y);
    bf_split(v.z, hv.z, lv.z);
    bf_split(v.w, hv.w, lv.w);
    reinterpret_cast<ushort4*>(g_xh)[i] = hv;
    reinterpret_cast<ushort4*>(g_xl)[i] = lv;
}

// One block per graph, 1024 threads: smem degree count -> smem scan ->
// smem CSR fill -> gather neighbor means; writes mean as bf16 hi/lo planes.
__global__ void __launch_bounds__(1024) k_aggregate(
        const int* __restrict__ src, const int* __restrict__ dst,
        const int* __restrict__ gec, int fixed,
        const float* __restrict__ xin, int n_per) {
    extern __shared__ int sm[];
    int* s_src = sm;                 // [EPG]
    int* s_dst = sm + EPG;           // [EPG] (local dst)
    int* s_csr = sm + 2 * EPG;       // [EPG]
    int* s_deg = sm + 3 * EPG;       // [512]
    int* s_st  = s_deg + 512;        // [512]
    int* s_cur = s_st + 512;         // [512]

    int b = blockIdx.x, t = threadIdx.x;
    int ne    = fixed ? EPG : gec[b];
    int ebase = b * EPG;
    int nbase = b * n_per;

    if (t < 512) s_deg[t] = 0;
    __syncthreads();

    for (int i = t; i < ne; i += blockDim.x) {
        int s = src[ebase + i];
        int d = dst[ebase + i] - nbase;
        s_src[i] = s;
        s_dst[i] = d;
        atomicAdd(&s_deg[d], 1);
    }
    __syncthreads();

    int v = (t < 512) ? s_deg[t] : 0;
    if (t < 512) s_st[t] = v;
    __syncthreads();
    #pragma unroll
    for (int o = 1; o < 512; o <<= 1) {
        int u = (t >= o && t < 512) ? s_st[t - o] : 0;
        __syncthreads();
        if (t < 512) s_st[t] += u;
        __syncthreads();
    }
    if (t < 512) {
        int excl = s_st[t] - v;
        s_st[t]  = excl;
        s_cur[t] = excl;
    }
    __syncthreads();

    for (int i = t; i < ne; i += blockDim.x) {
        int pos = atomicAdd(&s_cur[s_dst[i]], 1);
        s_csr[pos] = s_src[i];
    }
    __syncthreads();

    int lane = t & 31, wid = t >> 5, nw = blockDim.x >> 5;
    for (int node = wid; node < n_per; node += nw) {
        int deg = s_deg[node], st = s_st[node];
        float4 a0 = {0.f,0.f,0.f,0.f}, a1 = a0, a2 = a0, a3 = a0;
        int j = 0;
        for (; j + 4 <= deg; j += 4) {
            int s0 = s_csr[st + j];
            int s1 = s_csr[st + j + 1];
            int s2 = s_csr[st + j + 2];
            int s3 = s_csr[st + j + 3];
            float4 v0 = reinterpret_cast<const float4*>(xin + (size_t)s0 * H)[lane];
            float4 v1 = reinterpret_cast<const float4*>(xin + (size_t)s1 * H)[lane];
            float4 v2 = reinterpret_cast<const float4*>(xin + (size_t)s2 * H)[lane];
            float4 v3 = reinterpret_cast<const float4*>(xin + (size_t)s3 * H)[lane];
            a0.x += v0.x; a0.y += v0.y; a0.z += v0.z; a0.w += v0.w;
            a1.x += v1.x; a1.y += v1.y; a1.z += v1.z; a1.w += v1.w;
            a2.x += v2.x; a2.y += v2.y; a2.z += v2.z; a2.w += v2.w;
            a3.x += v3.x; a3.y += v3.y; a3.z += v3.z; a3.w += v3.w;
        }
        for (; j < deg; j++) {
            int s0 = s_csr[st + j];
            float4 v0 = reinterpret_cast<const float4*>(xin + (size_t)s0 * H)[lane];
            a0.x += v0.x; a0.y += v0.y; a0.z += v0.z; a0.w += v0.w;
        }
        float invd = 1.0f / fmaxf((float)deg, 1.0f);
        float4 o;
        o.x = (a0.x + a1.x + a2.x + a3.x) * invd;
        o.y = (a0.y + a1.y + a2.y + a3.y) * invd;
        o.z = (a0.z + a1.z + a2.z + a3.z) * invd;
        o.w = (a0.w + a1.w + a2.w + a3.w) * invd;
        ushort4 hv, lv;
        bf_split(o.x, hv.x, lv.x);
        bf_split(o.y, hv.y, lv.y);
        bf_split(o.z, hv.z, lv.z);
        bf_split(o.w, hv.w, lv.w);
        size_t off = (size_t)(nbase + node) * H + lane * 4;
        *reinterpret_cast<ushort4*>(g_mh + off) = hv;
        *reinterpret_cast<ushort4*>(g_ml + off) = lv;
    }
}

// ---- mma.sync bf16 SAGE GEMM: out = relu( [mean||x] @ [Wl;Wr] + bl ) ----
// A planes (mean/x, hi/lo) are pre-converted bf16 in global; staging is pure
// cp.async copy. 3 cross terms (hh, hl, lh); ll dropped (<=2^-16 rel).
// 512 threads, 16 warps as 4(m)x4(n), warp tile 32x32.
#define AP 136
#define WP 264
#define SM_WH 512
#define SM_WL (512 + 128*WP*2)
#define SM_AH (512 + 2*128*WP*2)
#define SM_AL (512 + 2*128*WP*2 + 128*AP*2)
#define SAGE_SMEM_TC (512 + 2*128*WP*2 + 2*128*AP*2)   // 205312 B

#define MMA_BF16(c0,c1,c2,c3, a0,a1,a2,a3, b0,b1) \
    asm volatile("mma.sync.aligned.m16n8k16.row.col.f32.bf16.bf16.f32 " \
        "{%0,%1,%2,%3}, {%4,%5,%6,%7}, {%8,%9}, {%0,%1,%2,%3};" \
        : "+f"(c0), "+f"(c1), "+f"(c2), "+f"(c3) \
        : "r"(a0), "r"(a1), "r"(a2), "r"(a3), "r"(b0), "r"(b1))

__global__ void __launch_bounds__(512) k_sage(const float* __restrict__ Wl,
                                              const float* __restrict__ bl,
                                              const float* __restrict__ Wr,
                                              float* __restrict__ out, int n) {
    extern __shared__ char smc[];
    float* sb = (float*)smc;                             // [128] bias
    unsigned short* sWH = (unsigned short*)(smc + SM_WH);
    unsigned short* sWL = (unsigned short*)(smc + SM_WL);
    unsigned short* sAH = (unsigned short*)(smc + SM_AH);
    unsigned short* sAL = (unsigned short*)(smc + SM_AL);
    uint32_t saH = smem_u32(sAH);
    uint32_t saL = smem_u32(sAL);

    int t = threadIdx.x;
    int wid = t >> 5, lane = t & 31;
    int g = lane >> 2, tq = lane & 3;
    int wm = wid & 3;             // 0..3 : m-offset 32*wm
    int wn = wid >> 2;            // 0..3 : n-offset 32*wn

    if (t < 128) sb[t] = bl[t];

    // Stage W transposed: Wt[n][kk], kk = m*128 + k; hi/lo bf16 split. Once per block.
    for (int m = 0; m < 2; m++) {
        const float* W = m ? Wr : Wl;
        for (int i = t; i < 128 * 32; i += 512) {
            int k = i >> 5, n4 = i & 31;
            float4 v = *reinterpret_cast<const float4*>(W + k * 128 + n4 * 4);
            int kk = m * 128 + k;
            float vv[4] = {v.x, v.y, v.z, v.w};
            #pragma unroll
            for (int e = 0; e < 4; e++) {
                int nn = n4 * 4 + e;
                unsigned short hb, lb;
                bf_split(vv[e], hb, lb);
                sWH[nn * WP + kk] = hb;
                sWL[nn * WP + kk] = lb;
            }
        }
    }
    __syncthreads();

    int ntiles = (n + 127) / 128;

    for (int tile = blockIdx.x; tile < ntiles; tile += gridDim.x) {
        int row0 = tile * 128;

        float acc[2][4][4];
        #pragma unroll
        for (int mt = 0; mt < 2; mt++)
            #pragma unroll
            for (int nt = 0; nt < 4; nt++)
                #pragma unroll
                for (int e = 0; e < 4; e++) acc[mt][nt][e] = 0.f;

        #pragma unroll
        for (int ph = 0; ph < 2; ph++) {
            const unsigned short* srcH = ph ? g_xh : g_mh;
            const unsigned short* srcL = ph ? g_xl : g_ml;
            __syncthreads();          // previous phase fragment readers done
            // stage A half: pure cp.async copy, 16B chunks (8 bf16)
            for (int i = t; i < 128 * 16; i += 512) {
                int r = i >> 4, c8 = (i & 15) << 3;
                int grow = row0 + r;
                int valid = (grow < n);
                size_t goff = (size_t)(valid ? grow : 0) * H + c8;
                int sz = valid ? 16 : 0;
                uint32_t soff = (uint32_t)(r * AP + c8) * 2;
                cp_async16(saH + soff, srcH + goff, sz);
                cp_async16(saL + soff, srcL + goff, sz);
            }
            CP_COMMIT();
            CP_WAIT0();
            __syncthreads();

            #pragma unroll
            for (int s = 0; s < 8; s++) {
                int k0 = s * 16;                 // local k within half
                int kg = ph * 128 + k0;          // global k within [0,256)
                // B fragments (4 n-tiles, hi+lo)
                uint32_t bh[4][2], blo[4][2];
                #pragma unroll
                for (int nt = 0; nt < 4; nt++) {
                    int nn = wn * 32 + nt * 8 + g;
                    bh[nt][0]  = *reinterpret_cast<const uint32_t*>(sWH + nn * WP + kg + 2 * tq);
                    bh[nt][1]  = *reinterpret_cast<const uint32_t*>(sWH + nn * WP + kg + 2 * tq + 8);
                    blo[nt][0] = *reinterpret_cast<const uint32_t*>(sWL + nn * WP + kg + 2 * tq);
                    blo[nt][1] = *reinterpret_cast<const uint32_t*>(sWL + nn * WP + kg + 2 * tq + 8);
                }
                // A fragments (2 m-tiles, hi+lo)
                uint32_t ah[2][4], alo[2][4];
                #pragma unroll
                for (int mt = 0; mt < 2; mt++) {
                    int m0 = wm * 32 + mt * 16 + g;
                    ah[mt][0]  = *reinterpret_cast<const uint32_t*>(sAH + m0 * AP + k0 + 2 * tq);
                    ah[mt][1]  = *reinterpret_cast<const uint32_t*>(sAH + (m0 + 8) * AP + k0 + 2 * tq);
                    ah[mt][2]  = *reinterpret_cast<const uint32_t*>(sAH + m0 * AP + k0 + 2 * tq + 8);
                    ah[mt][3]  = *reinterpret_cast<const uint32_t*>(sAH + (m0 + 8) * AP + k0 + 2 * tq + 8);
                    alo[mt][0] = *reinterpret_cast<const uint32_t*>(sAL + m0 * AP + k0 + 2 * tq);
                    alo[mt][1] = *reinterpret_cast<const uint32_t*>(sAL + (m0 + 8) * AP + k0 + 2 * tq);
                    alo[mt][2] = *reinterpret_cast<const uint32_t*>(sAL + m0 * AP + k0 + 2 * tq + 8);
                    alo[mt][3] = *reinterpret_cast<const uint32_t*>(sAL + (m0 + 8) * AP + k0 + 2 * tq + 8);
                }
                // 3 passes: hh, hl, lh
                #pragma unroll
                for (int mt = 0; mt < 2; mt++)
                    #pragma unroll
                    for (int nt = 0; nt < 4; nt++)
                        MMA_BF16(acc[mt][nt][0], acc[mt][nt][1], acc[mt][nt][2], acc[mt][nt][3],
                                 ah[mt][0], ah[mt][1], ah[mt][2], ah[mt][3], bh[nt][0], bh[nt][1]);
                #pragma unroll
                for (int mt = 0; mt < 2; mt++)
                    #pragma unroll
                    for (int nt = 0; nt < 4; nt++)
                        MMA_BF16(acc[mt][nt][0], acc[mt][nt][1], acc[mt][nt][2], acc[mt][nt][3],
                                 ah[mt][0], ah[mt][1], ah[mt][2], ah[mt][3], blo[nt][0], blo[nt][1]);
                #pragma unroll
                for (int mt = 0; mt < 2; mt++)
                    #pragma unroll
                    for (int nt = 0; nt < 4; nt++)
                        MMA_BF16(acc[mt][nt][0], acc[mt][nt][1], acc[mt][nt][2], acc[mt][nt][3],
                                 alo[mt][0], alo[mt][1], alo[mt][2], alo[mt][3], bh[nt][0], bh[nt][1]);
            }
        }

        // epilogue: bias + relu + store
        #pragma unroll
        for (int mt = 0; mt < 2; mt++) {
            int r0 = row0 + wm * 32 + mt * 16 + g;
            #pragma unroll
            for (int nt = 0; nt < 4; nt++) {
                int c = wn * 32 + nt * 8 + 2 * tq;
                float b0v = sb[c], b1v = sb[c + 1];
                if (r0 < n) {
                    float2 o;
                    o.x = fmaxf(acc[mt][nt][0] + b0v, 0.f);
                    o.y = fmaxf(acc[mt][nt][1] + b1v, 0.f);
                    *reinterpret_cast<float2*>(out + (size_t)r0 * H + c) = o;
                }
                if (r0 + 8 < n) {
                    float2 o;
                    o.x = fmaxf(acc[mt][nt][2] + b0v, 0.f);
                    o.y = fmaxf(acc[mt][nt][3] + b1v, 0.f);
                    *reinterpret_cast<float2*>(out + (size_t)(r0 + 8) * H + c) = o;
                }
            }
        }
    }
}

// One block per graph, 1024 threads: score + stable top-k + pool + readout +
// edge compact. Also writes pooled features as bf16 hi/lo planes.
__global__ void __launch_bounds__(1024) k_pool_all(
        const float* __restrict__ h, const float* __restrict__ pw,
        int n_per, int k, int layer,
        const int* __restrict__ src, const int* __restrict__ dst,
        const int* __restrict__ gec, int fixed,
        int* __restrict__ nsrc, int* __restrict__ ndst, int* __restrict__ ngec,
        float* __restrict__ hout) {
    __shared__ float s_w[128];
    __shared__ float s_sc[512];
    __shared__ int   s_map[512];
    __shared__ int   s_perm[256];
    __shared__ float s_inv;
    __shared__ int   s_cursor;
    __shared__ float s_mx[8][128];
    __shared__ float s_sm[8][128];

    int b = blockIdx.x, t = threadIdx.x;
    int lane = t & 31, wid = t >> 5, nw = blockDim.x >> 5;
    int nbase = b * n_per;

    if (t < 128) s_w[t] = pw[t];
    if (t == 0) s_cursor = 0;
    __syncthreads();

    if (wid == 0) {
        float wn = 0.f;
        #pragma unroll
        for (int c = lane; c < 128; c += 32) { float w = s_w[c]; wn += w * w; }
        #pragma unroll
        for (int o = 16; o; o >>= 1) wn += __shfl_down_sync(0xffffffffu, wn, o);
        if (lane == 0) s_inv = rsqrtf(wn);
    }
    __syncthreads();
    float inv = s_inv;

    // scores: warp per node (32 warps)
    for (int node = wid; node < n_per; node += nw) {
        const float* row = h + (size_t)(nbase + node) * H;
        float dot = 0.f;
        #pragma unroll
        for (int c = lane; c < 128; c += 32) dot += row[c] * s_w[c];
        #pragma unroll
        for (int o = 16; o; o >>= 1) dot += __shfl_down_sync(0xffffffffu, dot, o);
        if (lane == 0) s_sc[node] = tanhf(dot * inv);
    }
    __syncthreads();

    // stable top-k via rank counting (matches jax.lax.top_k tie-break)
    if (t < n_per) {
        float si = s_sc[t];
        int rank = 0;
        for (int j = 0; j < n_per; j++) {
            float sj = s_sc[j];
            rank += (sj > si) || (sj == si && j < t);
        }
        if (rank < k) { s_map[t] = rank; s_perm[rank] = t; }
        else          s_map[t] = -1;
    }
    __syncthreads();

    // pool: warp per kept rank
    for (int r = wid; r < k; r += nw) {
        int node = s_perm[r];
        float sc = s_sc[node];
        float4 v = reinterpret_cast<const float4*>(h + (size_t)(nbase + node) * H)[lane];
        v.x *= sc; v.y *= sc; v.z *= sc; v.w *= sc;
        size_t off = (size_t)(b * k + r) * H + lane * 4;
        *reinterpret_cast<float4*>(hout + off) = v;
        if (layer < 2) {
            ushort4 hv, lv;
            bf_split(v.x, hv.x, lv.x);
            bf_split(v.y, hv.y, lv.y);
            bf_split(v.z, hv.z, lv.z);
            bf_split(v.w, hv.w, lv.w);
            *reinterpret_cast<ushort4*>(g_xh + off) = hv;
            *reinterpret_cast<ushort4*>(g_xl + off) = lv;
        }
    }
    __syncthreads();

    // readout: max||mean over k pooled rows, 8-way parallel over rows
    {
        int q = t >> 7;          // 0..7
        int c = t & 127;
        float mx = -1e30f, smv = 0.f;
        for (int r = q; r < k; r += 8) {
            float v = hout[(size_t)(b * k + r) * H + c];
            mx = fmaxf(mx, v);
            smv += v;
        }
        s_mx[q][c] = mx;
        s_sm[q][c] = smv;
    }
    __syncthreads();
    if (t < 128) {
        float mx = s_mx[0][t], smv = s_sm[0][t];
        #pragma unroll
        for (int q = 1; q < 8; q++) {
            mx = fmaxf(mx, s_mx[q][t]);
            smv += s_sm[q][t];
        }
        float mean = smv / (float)k;
        if (layer == 0) {
            g_z[b * 2 * H + t]     = mx;
            g_z[b * 2 * H + H + t] = mean;
        } else {
            g_z[b * 2 * H + t]     += mx;
            g_z[b * 2 * H + H + t] += mean;
        }
    }

    // edge remap + compact into next layer's per-graph region
    if (layer < 2) {
        int ne = fixed ? EPG : gec[b];
        int ebase = b * EPG;
        for (int e0 = 0; e0 < ne; e0 += blockDim.x) {
            int e = e0 + t;
            int rs = -1, rd = -1;
            if (e < ne) {
                rs = s_map[src[ebase + e] - nbase];
                rd = s_map[dst[ebase + e] - nbase];
            }
            bool act = (rs >= 0) && (rd >= 0);
            unsigned m = __ballot_sync(0xffffffffu, act);
            if (m) {
                int leader = __ffs(m) - 1;
                int base = 0;
                if (lane == leader) base = atomicAdd(&s_cursor, __popc(m));
                base = __shfl_sync(0xffffffffu, base, leader);
                if (act) {
                    int pos = base + __popc(m & ((1u << lane) - 1u));
                    nsrc[ebase + pos] = b * k + rs;
                    ndst[ebase + pos] = b * k + rd;
                }
            }
        }
        __syncthreads();
        if (t == 0) ngec[b] = s_cursor;
    }
}

// MLP head + log_softmax, one block per graph
__global__ void k_mlp(const float* __restrict__ W1, const float* __restrict__ b1,
                      const float* __restrict__ W2, const float* __restrict__ b2,
                      const float* __restrict__ W3, const float* __restrict__ b3,
                      float* __restrict__ out) {
    int b = blockIdx.x, t = threadIdx.x;
    __shared__ float zin[256], t1[128], t2[64], lg[10];
    zin[t] = g_z[b * 256 + t];
    __syncthreads();
    if (t < 128) {
        float a = b1[t];
        for (int k = 0; k < 256; k++) a += zin[k] * W1[k * 128 + t];
        t1[t] = fmaxf(a, 0.f);
    }
    __syncthreads();
    if (t < 64) {
        float a = b2[t];
        for (int k = 0; k < 128; k++) a += t1[k] * W2[k * 64 + t];
        t2[t] = fmaxf(a, 0.f);
    }
    __syncthreads();
    if (t < 10) {
        float a = b3[t];
        for (int k = 0; k < 64; k++) a += t2[k] * W3[k * 10 + t];
        lg[t] = a;
    }
    __syncthreads();
    if (t == 0) {
        float mx = -1e30f;
        for (int i = 0; i < 10; i++) mx = fmaxf(mx, lg[i]);
        float s = 0.f;
        for (int i = 0; i < 10; i++) s += expf(lg[i] - mx);
        float lse = mx + logf(s);
        for (int i = 0; i < 10; i++) out[b * 10 + i] = lg[i] - lse;
    }
}

// ---------------- host ----------------

static const int AGG_SMEM = (3 * EPG + 3 * 512) * sizeof(int);  // 78144 B

extern "C" void kernel_launch(void* const* d_in, const int* in_sizes, int n_in,
                              void* d_out, int out_size) {
    const float* x   = (const float*)d_in[0];
    const int*   ei  = (const int*)  d_in[1];
    const float* Wl1 = (const float*)d_in[2];
    const float* bl1 = (const float*)d_in[3];
    const float* Wr1 = (const float*)d_in[4];
    const float* Wl2 = (const float*)d_in[5];
    const float* bl2 = (const float*)d_in[6];
    const float* Wr2 = (const float*)d_in[7];
    const float* Wl3 = (const float*)d_in[8];
    const float* bl3 = (const float*)d_in[9];
    const float* Wr3 = (const float*)d_in[10];
    const float* pw1 = (const float*)d_in[11];
    const float* pw2 = (const float*)d_in[12];
    const float* pw3 = (const float*)d_in[13];
    const float* W1  = (const float*)d_in[14];
    const float* b1  = (const float*)d_in[15];
    const float* W2  = (const float*)d_in[16];
    const float* b2  = (const float*)d_in[17];
    const float* W3  = (const float*)d_in[18];
    const float* b3  = (const float*)d_in[19];
    float* out = (float*)d_out;

    static bool attr_set = false;
    if (!attr_set) {
        cudaFuncSetAttribute(k_sage,      cudaFuncAttributeMaxDynamicSharedMemorySize, SAGE_SMEM_TC);
        cudaFuncSetAttribute(k_aggregate, cudaFuncAttributeMaxDynamicSharedMemorySize, AGG_SMEM);
        attr_set = true;
    }

    void *p_h, *p_p1, *p_p2, *p_srcB, *p_dstB, *p_srcC, *p_dstC, *p_gecB, *p_gecC;
    cudaGetSymbolAddress(&p_h,    g_h);
    cudaGetSymbolAddress(&p_p1,   g_p1);
    cudaGetSymbolAddress(&p_p2,   g_p2);
    cudaGetSymbolAddress(&p_srcB, g_srcB);
    cudaGetSymbolAddress(&p_dstB, g_dstB);
    cudaGetSymbolAddress(&p_srcC, g_srcC);
    cudaGetSymbolAddress(&p_dstC, g_dstC);
    cudaGetSymbolAddress(&p_gecB, g_gecB);
    cudaGetSymbolAddress(&p_gecC, g_gecC);
    float* dh = (float*)p_h;

    struct Layer {
        const float *Wl, *bl, *Wr, *pw;
        const int *src, *dst, *gec;
        int fixed;
        int *nsrc, *ndst, *ngec;
        int n_in, n_per, k;
        float* pool_out;
    } layers[3] = {
        {Wl1, bl1, Wr1, pw1, ei,           ei + NE,      nullptr,       1,
         (int*)p_srcB, (int*)p_dstB, (int*)p_gecB, NN,      NPG, K1, (float*)p_p1},
        {Wl2, bl2, Wr2, pw2, (int*)p_srcB, (int*)p_dstB, (int*)p_gecB,  0,
         (int*)p_srcC, (int*)p_dstC, (int*)p_gecC, NB * K1, K1,  K2, (float*)p_p2},
        {Wl3, bl3, Wr3, pw3, (int*)p_srcC, (int*)p_dstC, (int*)p_gecC,  0,
         nullptr, nullptr, nullptr,                  NB * K2, K2,  K3, (float*)p_p1},
    };

    // one-shot conversion of the layer-1 x operand to bf16 hi/lo planes
    k_convert_x<<<(NN * H / 4 + 255) / 256, 256>>>(x);

    const float* xin = x;
    for (int l = 0; l < 3; l++) {
        const Layer& L = layers[l];
        int n = L.n_in;

        k_aggregate<<<NB, 1024, AGG_SMEM>>>(L.src, L.dst, L.gec, L.fixed, xin, L.n_per);

        int ntiles = (n + 127) / 128;
        int grid = ntiles < 148 ? ntiles : 148;
        k_sage<<<grid, 512, SAGE_SMEM_TC>>>(L.Wl, L.bl, L.Wr, dh, n);

        k_pool_all<<<NB, 1024>>>(dh, L.pw, L.n_per, L.k, l,
                                 L.src, L.dst, L.gec, L.fixed,
                                 L.nsrc, L.ndst, L.ngec, L.pool_out);

        xin = L.pool_out;
    }

    k_mlp<<<NB, 256>>>(W1, b1, W2, b2, W3, b3, out);
}